// round 1
// baseline (speedup 1.0000x reference)
#include <cuda_runtime.h>
#include <math.h>

// Problem constants
#define NTOK 4096       // B*T
#define EMB  1024
#define HID  4096
#define VOCAB 32000
#define SEQ  2048
#define NH   16
#define HD   64
#define NL   8

// ---------------- scratch (device globals; no cudaMalloc allowed) ----------
__device__ float g_x[NTOK * EMB];
__device__ float g_h[NTOK * EMB];
__device__ float g_q[NTOK * EMB];
__device__ float g_k[NTOK * EMB];
__device__ float g_v[NTOK * EMB];
__device__ float g_o[NTOK * EMB];
__device__ float g_u[NTOK * HID];

// ---------------- embed: x = tok_emb[idx] + pos_emb[t] ---------------------
__global__ void embed_kernel(const int* __restrict__ idx,
                             const float* __restrict__ tok,
                             const float* __restrict__ pos,
                             float* __restrict__ x) {
    int n = blockIdx.x;              // token row
    int e4 = threadIdx.x;            // 0..255, one float4 each
    int t = n & (SEQ - 1);
    const float4* tr = (const float4*)(tok + (size_t)idx[n] * EMB);
    const float4* pr = (const float4*)(pos + (size_t)t * EMB);
    float4 a = tr[e4];
    float4 b = pr[e4];
    a.x += b.x; a.y += b.y; a.z += b.z; a.w += b.w;
    ((float4*)(x + (size_t)n * EMB))[e4] = a;
}

// ---------------- block reduce (256 threads) --------------------------------
__device__ __forceinline__ float block_sum_256(float s, float* red) {
    #pragma unroll
    for (int o = 16; o; o >>= 1) s += __shfl_xor_sync(0xffffffffu, s, o);
    if ((threadIdx.x & 31) == 0) red[threadIdx.x >> 5] = s;
    __syncthreads();
    if (threadIdx.x < 32) {
        float t = (threadIdx.x < 8) ? red[threadIdx.x] : 0.0f;
        #pragma unroll
        for (int o = 4; o; o >>= 1) t += __shfl_xor_sync(0xffffffffu, t, o);
        if (threadIdx.x == 0) red[0] = t;
    }
    __syncthreads();
    float r = red[0];
    __syncthreads();
    return r;
}

// ---------------- layernorm (two-pass, matches reference) -------------------
__global__ void ln_kernel(const float* __restrict__ x,
                          const float* __restrict__ g,
                          const float* __restrict__ b,
                          float* __restrict__ out) {
    __shared__ float red[8];
    int n = blockIdx.x;
    int tid = threadIdx.x;           // 256 threads, 4 elems each
    float4 v = ((const float4*)(x + (size_t)n * EMB))[tid];
    float s = v.x + v.y + v.z + v.w;
    float mu = block_sum_256(s, red) * (1.0f / EMB);
    float dx = v.x - mu, dy = v.y - mu, dz = v.z - mu, dw = v.w - mu;
    float s2 = dx * dx + dy * dy + dz * dz + dw * dw;
    float var = block_sum_256(s2, red) * (1.0f / EMB);
    float rs = rsqrtf(var + 1e-5f);
    float4 gg = ((const float4*)g)[tid];
    float4 bb = ((const float4*)b)[tid];
    float4 r;
    r.x = dx * rs * gg.x + bb.x;
    r.y = dy * rs * gg.y + bb.y;
    r.z = dz * rs * gg.z + bb.z;
    r.w = dw * rs * gg.w + bb.w;
    ((float4*)(out + (size_t)n * EMB))[tid] = r;
}

// ---------------- SGEMM: C = op(A @ B [+ bias]) [+ res] --------------------
// A: [M,K] row-major, B: [K,N] row-major. 128x128 tile, BK=16, 8x8/thread.
#define BM 128
#define BN 128
#define BK 16
#define FLAG_BIAS 1
#define FLAG_GELU 2
#define FLAG_RES  4

__global__ __launch_bounds__(256) void sgemm_kernel(
    const float* __restrict__ A, const float* __restrict__ B,
    const float* __restrict__ bias, const float* __restrict__ res,
    float* __restrict__ C, int M, int N, int K, int flags) {
    __shared__ float As[BK][BM];
    __shared__ float Bs[BK][BN];

    int tid = threadIdx.x;
    int tx = tid & 15;               // 0..15 (col group)
    int ty = tid >> 4;               // 0..15 (row group)
    int rowBase = blockIdx.y * BM;
    int colBase = blockIdx.x * BN;

    float acc[8][8];
    #pragma unroll
    for (int i = 0; i < 8; i++)
        #pragma unroll
        for (int j = 0; j < 8; j++) acc[i][j] = 0.0f;

    for (int k0 = 0; k0 < K; k0 += BK) {
        // load A tile (BM x BK), store transposed As[k][m]
        #pragma unroll
        for (int i = 0; i < 2; i++) {
            int idx4 = tid * 2 + i;          // 0..511
            int ar = idx4 >> 2;              // 0..127
            int ac4 = idx4 & 3;              // 0..3
            float4 av = *(const float4*)(A + (size_t)(rowBase + ar) * K + k0 + ac4 * 4);
            As[ac4 * 4 + 0][ar] = av.x;
            As[ac4 * 4 + 1][ar] = av.y;
            As[ac4 * 4 + 2][ar] = av.z;
            As[ac4 * 4 + 3][ar] = av.w;
        }
        // load B tile (BK x BN)
        #pragma unroll
        for (int i = 0; i < 2; i++) {
            int idx4 = tid * 2 + i;
            int br = idx4 >> 5;              // 0..15
            int bc4 = idx4 & 31;             // 0..31
            *(float4*)(&Bs[br][bc4 * 4]) =
                *(const float4*)(B + (size_t)(k0 + br) * N + colBase + bc4 * 4);
        }
        __syncthreads();

        #pragma unroll
        for (int kk = 0; kk < BK; kk++) {
            float4 a0 = *(const float4*)(&As[kk][ty * 8]);
            float4 a1 = *(const float4*)(&As[kk][ty * 8 + 4]);
            float4 b0 = *(const float4*)(&Bs[kk][tx * 8]);
            float4 b1 = *(const float4*)(&Bs[kk][tx * 8 + 4]);
            float af[8] = {a0.x, a0.y, a0.z, a0.w, a1.x, a1.y, a1.z, a1.w};
            float bf[8] = {b0.x, b0.y, b0.z, b0.w, b1.x, b1.y, b1.z, b1.w};
            #pragma unroll
            for (int i = 0; i < 8; i++)
                #pragma unroll
                for (int j = 0; j < 8; j++)
                    acc[i][j] = fmaf(af[i], bf[j], acc[i][j]);
        }
        __syncthreads();
    }

    // epilogue
    float bvals[8];
    if (flags & FLAG_BIAS) {
        float4 q0 = *(const float4*)(bias + colBase + tx * 8);
        float4 q1 = *(const float4*)(bias + colBase + tx * 8 + 4);
        bvals[0] = q0.x; bvals[1] = q0.y; bvals[2] = q0.z; bvals[3] = q0.w;
        bvals[4] = q1.x; bvals[5] = q1.y; bvals[6] = q1.z; bvals[7] = q1.w;
    }
    #pragma unroll
    for (int i = 0; i < 8; i++) {
        size_t row = (size_t)(rowBase + ty * 8 + i);
        float* crow = C + row * N + colBase + tx * 8;
        float vals[8];
        #pragma unroll
        for (int j = 0; j < 8; j++) {
            float v = acc[i][j];
            if (flags & FLAG_BIAS) v += bvals[j];
            if (flags & FLAG_GELU) v = 0.5f * v * (1.0f + erff(v * 0.70710678118654752f));
            vals[j] = v;
        }
        if (flags & FLAG_RES) {
            const float* rrow = res + row * N + colBase + tx * 8;
            float4 r0 = *(const float4*)(rrow);
            float4 r1 = *(const float4*)(rrow + 4);
            vals[0] += r0.x; vals[1] += r0.y; vals[2] += r0.z; vals[3] += r0.w;
            vals[4] += r1.x; vals[5] += r1.y; vals[6] += r1.z; vals[7] += r1.w;
        }
        *(float4*)(crow)     = make_float4(vals[0], vals[1], vals[2], vals[3]);
        *(float4*)(crow + 4) = make_float4(vals[4], vals[5], vals[6], vals[7]);
    }
}

// ---------------- attention: per (b,h,query-row) causal softmax -------------
// q,k,v: [B*T, E] with head h at cols [h*64, h*64+64)
__global__ __launch_bounds__(128) void attn_kernel(
    const float* __restrict__ q, const float* __restrict__ k,
    const float* __restrict__ v, float* __restrict__ o) {
    __shared__ float qs[HD];
    __shared__ float sc[SEQ];
    __shared__ float red[128];

    int t = blockIdx.x;
    int bh = blockIdx.y;
    int b = bh >> 4;
    int h = bh & 15;
    int tid = threadIdx.x;
    size_t base = (size_t)(b * SEQ) * EMB + h * HD;

    if (tid < 16)
        ((float4*)qs)[tid] = ((const float4*)(q + base + (size_t)t * EMB))[tid];
    __syncthreads();

    int nk = t + 1;
    float lmax = -1e30f;
    for (int s = tid; s < nk; s += 128) {
        const float4* kr = (const float4*)(k + base + (size_t)s * EMB);
        float a = 0.0f;
        #pragma unroll
        for (int d4 = 0; d4 < 16; d4++) {
            float4 kv = kr[d4];
            a = fmaf(qs[d4 * 4 + 0], kv.x, a);
            a = fmaf(qs[d4 * 4 + 1], kv.y, a);
            a = fmaf(qs[d4 * 4 + 2], kv.z, a);
            a = fmaf(qs[d4 * 4 + 3], kv.w, a);
        }
        a *= 0.125f;                 // 1/sqrt(64)
        sc[s] = a;
        lmax = fmaxf(lmax, a);
    }
    red[tid] = lmax;
    __syncthreads();
    #pragma unroll
    for (int s = 64; s; s >>= 1) {
        if (tid < s) red[tid] = fmaxf(red[tid], red[tid + s]);
        __syncthreads();
    }
    float m = red[0];
    __syncthreads();

    float lsum = 0.0f;
    for (int s = tid; s < nk; s += 128) {
        float p = __expf(sc[s] - m);
        sc[s] = p;
        lsum += p;
    }
    red[tid] = lsum;
    __syncthreads();
    #pragma unroll
    for (int s = 64; s; s >>= 1) {
        if (tid < s) red[tid] += red[tid + s];
        __syncthreads();
    }
    float inv = 1.0f / red[0];
    __syncthreads();

    int d = tid & 63;
    int g = tid >> 6;
    float acc = 0.0f;
    for (int s = g; s < nk; s += 2)
        acc = fmaf(sc[s], v[base + (size_t)s * EMB + d], acc);
    red[tid] = acc;
    __syncthreads();
    if (tid < 64)
        o[base + (size_t)t * EMB + tid] = (red[tid] + red[tid + 64]) * inv;
}

// ---------------- launch ----------------------------------------------------
extern "C" void kernel_launch(void* const* d_in, const int* in_sizes, int n_in,
                              void* d_out, int out_size) {
    const int*   idx    = (const int*)d_in[0];
    const float* tok    = (const float*)d_in[1];
    const float* pos    = (const float*)d_in[2];
    const float* Wq     = (const float*)d_in[3];
    const float* Wk     = (const float*)d_in[4];
    const float* Wv     = (const float*)d_in[5];
    const float* Wp     = (const float*)d_in[6];
    const float* bp     = (const float*)d_in[7];
    const float* ln1_g  = (const float*)d_in[8];
    const float* ln1_b  = (const float*)d_in[9];
    const float* ln2_g  = (const float*)d_in[10];
    const float* ln2_b  = (const float*)d_in[11];
    const float* W1     = (const float*)d_in[12];
    const float* b1     = (const float*)d_in[13];
    const float* W2     = (const float*)d_in[14];
    const float* b2     = (const float*)d_in[15];
    const float* lnf_g  = (const float*)d_in[16];
    const float* lnf_b  = (const float*)d_in[17];
    const float* Wout   = (const float*)d_in[18];

    float *x, *h, *q, *k, *v, *o, *u;
    cudaGetSymbolAddress((void**)&x, g_x);
    cudaGetSymbolAddress((void**)&h, g_h);
    cudaGetSymbolAddress((void**)&q, g_q);
    cudaGetSymbolAddress((void**)&k, g_k);
    cudaGetSymbolAddress((void**)&v, g_v);
    cudaGetSymbolAddress((void**)&o, g_o);
    cudaGetSymbolAddress((void**)&u, g_u);

    embed_kernel<<<NTOK, 256>>>(idx, tok, pos, x);

    dim3 gE(EMB / BN, NTOK / BM);      // 8 x 32
    dim3 gH(HID / BN, NTOK / BM);      // 32 x 32
    dim3 gV(VOCAB / BN, NTOK / BM);    // 250 x 32
    dim3 gA(SEQ, 2 * NH);              // 2048 x 32

    for (int l = 0; l < NL; l++) {
        const float* wq = Wq + (size_t)l * EMB * EMB;
        const float* wk = Wk + (size_t)l * EMB * EMB;
        const float* wv = Wv + (size_t)l * EMB * EMB;
        const float* wp = Wp + (size_t)l * EMB * EMB;
        const float* w1 = W1 + (size_t)l * EMB * HID;
        const float* w2 = W2 + (size_t)l * HID * EMB;

        ln_kernel<<<NTOK, 256>>>(x, ln1_g + l * EMB, ln1_b + l * EMB, h);
        sgemm_kernel<<<gE, 256>>>(h, wq, nullptr, nullptr, q, NTOK, EMB, EMB, 0);
        sgemm_kernel<<<gE, 256>>>(h, wk, nullptr, nullptr, k, NTOK, EMB, EMB, 0);
        sgemm_kernel<<<gE, 256>>>(h, wv, nullptr, nullptr, v, NTOK, EMB, EMB, 0);
        attn_kernel<<<gA, 128>>>(q, k, v, o);
        sgemm_kernel<<<gE, 256>>>(o, wp, bp + l * EMB, x, x, NTOK, EMB, EMB,
                                  FLAG_BIAS | FLAG_RES);
        ln_kernel<<<NTOK, 256>>>(x, ln2_g + l * EMB, ln2_b + l * EMB, h);
        sgemm_kernel<<<gH, 256>>>(h, w1, b1 + l * HID, nullptr, u, NTOK, HID, EMB,
                                  FLAG_BIAS | FLAG_GELU);
        sgemm_kernel<<<gE, 256>>>(u, w2, b2 + l * EMB, x, x, NTOK, EMB, HID,
                                  FLAG_BIAS | FLAG_RES);
    }

    ln_kernel<<<NTOK, 256>>>(x, lnf_g, lnf_b, h);
    sgemm_kernel<<<gV, 256>>>(h, Wout, nullptr, nullptr, (float*)d_out,
                              NTOK, VOCAB, EMB, 0);
}

// round 2
// speedup vs baseline: 1.0023x; 1.0023x over previous
#include <cuda_runtime.h>
#include <math.h>

// Problem constants
#define NTOK 4096       // B*T
#define EMB  1024
#define HID  4096
#define VOCAB 32000
#define SEQ  2048
#define NH   16
#define HD   64
#define NL   8

// ---------------- scratch (device globals; no cudaMalloc allowed) ----------
__device__ float g_x[NTOK * EMB];
__device__ float g_h[NTOK * EMB];
__device__ float g_q[NTOK * EMB];
__device__ float g_k[NTOK * EMB];
__device__ float g_v[NTOK * EMB];
__device__ float g_o[NTOK * EMB];
__device__ float g_u[NTOK * HID];

// ---------------- embed: x = tok_emb[idx] + pos_emb[t] ---------------------
__global__ void embed_kernel(const int* __restrict__ idx,
                             const float* __restrict__ tok,
                             const float* __restrict__ pos,
                             float* __restrict__ x) {
    int n = blockIdx.x;              // token row
    int e4 = threadIdx.x;            // 0..255, one float4 each
    int t = n & (SEQ - 1);
    const float4* tr = (const float4*)(tok + (size_t)idx[n] * EMB);
    const float4* pr = (const float4*)(pos + (size_t)t * EMB);
    float4 a = tr[e4];
    float4 b = pr[e4];
    a.x += b.x; a.y += b.y; a.z += b.z; a.w += b.w;
    ((float4*)(x + (size_t)n * EMB))[e4] = a;
}

// ---------------- block reduce (256 threads) --------------------------------
__device__ __forceinline__ float block_sum_256(float s, float* red) {
    #pragma unroll
    for (int o = 16; o; o >>= 1) s += __shfl_xor_sync(0xffffffffu, s, o);
    if ((threadIdx.x & 31) == 0) red[threadIdx.x >> 5] = s;
    __syncthreads();
    if (threadIdx.x < 32) {
        float t = (threadIdx.x < 8) ? red[threadIdx.x] : 0.0f;
        #pragma unroll
        for (int o = 4; o; o >>= 1) t += __shfl_xor_sync(0xffffffffu, t, o);
        if (threadIdx.x == 0) red[0] = t;
    }
    __syncthreads();
    float r = red[0];
    __syncthreads();
    return r;
}

// ---------------- layernorm (two-pass, matches reference) -------------------
__global__ void ln_kernel(const float* __restrict__ x,
                          const float* __restrict__ g,
                          const float* __restrict__ b,
                          float* __restrict__ out) {
    __shared__ float red[8];
    int n = blockIdx.x;
    int tid = threadIdx.x;           // 256 threads, 4 elems each
    float4 v = ((const float4*)(x + (size_t)n * EMB))[tid];
    float s = v.x + v.y + v.z + v.w;
    float mu = block_sum_256(s, red) * (1.0f / EMB);
    float dx = v.x - mu, dy = v.y - mu, dz = v.z - mu, dw = v.w - mu;
    float s2 = dx * dx + dy * dy + dz * dz + dw * dw;
    float var = block_sum_256(s2, red) * (1.0f / EMB);
    float rs = rsqrtf(var + 1e-5f);
    float4 gg = ((const float4*)g)[tid];
    float4 bb = ((const float4*)b)[tid];
    float4 r;
    r.x = dx * rs * gg.x + bb.x;
    r.y = dy * rs * gg.y + bb.y;
    r.z = dz * rs * gg.z + bb.z;
    r.w = dw * rs * gg.w + bb.w;
    ((float4*)(out + (size_t)n * EMB))[tid] = r;
}

// ---------------- SGEMM: C = op(A @ B [+ bias]) [+ res] --------------------
// A: [M,K] row-major, B: [K,N] row-major. 128x128 tile, BK=16, 8x8/thread.
#define BM 128
#define BN 128
#define BK 16
#define FLAG_BIAS 1
#define FLAG_GELU 2
#define FLAG_RES  4

__global__ __launch_bounds__(256) void sgemm_kernel(
    const float* __restrict__ A, const float* __restrict__ B,
    const float* __restrict__ bias, const float* __restrict__ res,
    float* __restrict__ C, int M, int N, int K, int flags) {
    __shared__ float As[BK][BM];
    __shared__ float Bs[BK][BN];

    int tid = threadIdx.x;
    int tx = tid & 15;               // 0..15 (col group)
    int ty = tid >> 4;               // 0..15 (row group)
    int rowBase = blockIdx.y * BM;
    int colBase = blockIdx.x * BN;

    float acc[8][8];
    #pragma unroll
    for (int i = 0; i < 8; i++)
        #pragma unroll
        for (int j = 0; j < 8; j++) acc[i][j] = 0.0f;

    for (int k0 = 0; k0 < K; k0 += BK) {
        // load A tile (BM x BK), store transposed As[k][m]
        #pragma unroll
        for (int i = 0; i < 2; i++) {
            int idx4 = tid * 2 + i;          // 0..511
            int ar = idx4 >> 2;              // 0..127
            int ac4 = idx4 & 3;              // 0..3
            float4 av = *(const float4*)(A + (size_t)(rowBase + ar) * K + k0 + ac4 * 4);
            As[ac4 * 4 + 0][ar] = av.x;
            As[ac4 * 4 + 1][ar] = av.y;
            As[ac4 * 4 + 2][ar] = av.z;
            As[ac4 * 4 + 3][ar] = av.w;
        }
        // load B tile (BK x BN)
        #pragma unroll
        for (int i = 0; i < 2; i++) {
            int idx4 = tid * 2 + i;
            int br = idx4 >> 5;              // 0..15
            int bc4 = idx4 & 31;             // 0..31
            *(float4*)(&Bs[br][bc4 * 4]) =
                *(const float4*)(B + (size_t)(k0 + br) * N + colBase + bc4 * 4);
        }
        __syncthreads();

        #pragma unroll
        for (int kk = 0; kk < BK; kk++) {
            float4 a0 = *(const float4*)(&As[kk][ty * 8]);
            float4 a1 = *(const float4*)(&As[kk][ty * 8 + 4]);
            float4 b0 = *(const float4*)(&Bs[kk][tx * 8]);
            float4 b1 = *(const float4*)(&Bs[kk][tx * 8 + 4]);
            float af[8] = {a0.x, a0.y, a0.z, a0.w, a1.x, a1.y, a1.z, a1.w};
            float bf[8] = {b0.x, b0.y, b0.z, b0.w, b1.x, b1.y, b1.z, b1.w};
            #pragma unroll
            for (int i = 0; i < 8; i++)
                #pragma unroll
                for (int j = 0; j < 8; j++)
                    acc[i][j] = fmaf(af[i], bf[j], acc[i][j]);
        }
        __syncthreads();
    }

    // epilogue
    float bvals[8];
    if (flags & FLAG_BIAS) {
        float4 q0 = *(const float4*)(bias + colBase + tx * 8);
        float4 q1 = *(const float4*)(bias + colBase + tx * 8 + 4);
        bvals[0] = q0.x; bvals[1] = q0.y; bvals[2] = q0.z; bvals[3] = q0.w;
        bvals[4] = q1.x; bvals[5] = q1.y; bvals[6] = q1.z; bvals[7] = q1.w;
    }
    #pragma unroll
    for (int i = 0; i < 8; i++) {
        size_t row = (size_t)(rowBase + ty * 8 + i);
        float* crow = C + row * N + colBase + tx * 8;
        float vals[8];
        #pragma unroll
        for (int j = 0; j < 8; j++) {
            float v = acc[i][j];
            if (flags & FLAG_BIAS) v += bvals[j];
            if (flags & FLAG_GELU) v = 0.5f * v * (1.0f + erff(v * 0.70710678118654752f));
            vals[j] = v;
        }
        if (flags & FLAG_RES) {
            const float* rrow = res + row * N + colBase + tx * 8;
            float4 r0 = *(const float4*)(rrow);
            float4 r1 = *(const float4*)(rrow + 4);
            vals[0] += r0.x; vals[1] += r0.y; vals[2] += r0.z; vals[3] += r0.w;
            vals[4] += r1.x; vals[5] += r1.y; vals[6] += r1.z; vals[7] += r1.w;
        }
        *(float4*)(crow)     = make_float4(vals[0], vals[1], vals[2], vals[3]);
        *(float4*)(crow + 4) = make_float4(vals[4], vals[5], vals[6], vals[7]);
    }
}

// ---------------- attention: per (b,h,query-row) causal softmax -------------
// q,k,v: [B*T, E] with head h at cols [h*64, h*64+64)
__global__ __launch_bounds__(128) void attn_kernel(
    const float* __restrict__ q, const float* __restrict__ k,
    const float* __restrict__ v, float* __restrict__ o) {
    __shared__ float qs[HD];
    __shared__ float sc[SEQ];
    __shared__ float red[128];

    int t = blockIdx.x;
    int bh = blockIdx.y;
    int b = bh >> 4;
    int h = bh & 15;
    int tid = threadIdx.x;
    size_t base = (size_t)(b * SEQ) * EMB + h * HD;

    if (tid < 16)
        ((float4*)qs)[tid] = ((const float4*)(q + base + (size_t)t * EMB))[tid];
    __syncthreads();

    int nk = t + 1;
    float lmax = -1e30f;
    for (int s = tid; s < nk; s += 128) {
        const float4* kr = (const float4*)(k + base + (size_t)s * EMB);
        float a = 0.0f;
        #pragma unroll
        for (int d4 = 0; d4 < 16; d4++) {
            float4 kv = kr[d4];
            a = fmaf(qs[d4 * 4 + 0], kv.x, a);
            a = fmaf(qs[d4 * 4 + 1], kv.y, a);
            a = fmaf(qs[d4 * 4 + 2], kv.z, a);
            a = fmaf(qs[d4 * 4 + 3], kv.w, a);
        }
        a *= 0.125f;                 // 1/sqrt(64)
        sc[s] = a;
        lmax = fmaxf(lmax, a);
    }
    red[tid] = lmax;
    __syncthreads();
    #pragma unroll
    for (int s = 64; s; s >>= 1) {
        if (tid < s) red[tid] = fmaxf(red[tid], red[tid + s]);
        __syncthreads();
    }
    float m = red[0];
    __syncthreads();

    float lsum = 0.0f;
    for (int s = tid; s < nk; s += 128) {
        float p = __expf(sc[s] - m);
        sc[s] = p;
        lsum += p;
    }
    red[tid] = lsum;
    __syncthreads();
    #pragma unroll
    for (int s = 64; s; s >>= 1) {
        if (tid < s) red[tid] += red[tid + s];
        __syncthreads();
    }
    float inv = 1.0f / red[0];
    __syncthreads();

    int d = tid & 63;
    int g = tid >> 6;
    float acc = 0.0f;
    for (int s = g; s < nk; s += 2)
        acc = fmaf(sc[s], v[base + (size_t)s * EMB + d], acc);
    red[tid] = acc;
    __syncthreads();
    if (tid < 64)
        o[base + (size_t)t * EMB + tid] = (red[tid] + red[tid + 64]) * inv;
}

// ---------------- launch ----------------------------------------------------
extern "C" void kernel_launch(void* const* d_in, const int* in_sizes, int n_in,
                              void* d_out, int out_size) {
    const int*   idx    = (const int*)d_in[0];
    const float* tok    = (const float*)d_in[1];
    const float* pos    = (const float*)d_in[2];
    const float* Wq     = (const float*)d_in[3];
    const float* Wk     = (const float*)d_in[4];
    const float* Wv     = (const float*)d_in[5];
    const float* Wp     = (const float*)d_in[6];
    const float* bp     = (const float*)d_in[7];
    const float* ln1_g  = (const float*)d_in[8];
    const float* ln1_b  = (const float*)d_in[9];
    const float* ln2_g  = (const float*)d_in[10];
    const float* ln2_b  = (const float*)d_in[11];
    const float* W1     = (const float*)d_in[12];
    const float* b1     = (const float*)d_in[13];
    const float* W2     = (const float*)d_in[14];
    const float* b2     = (const float*)d_in[15];
    const float* lnf_g  = (const float*)d_in[16];
    const float* lnf_b  = (const float*)d_in[17];
    const float* Wout   = (const float*)d_in[18];

    float *x, *h, *q, *k, *v, *o, *u;
    cudaGetSymbolAddress((void**)&x, g_x);
    cudaGetSymbolAddress((void**)&h, g_h);
    cudaGetSymbolAddress((void**)&q, g_q);
    cudaGetSymbolAddress((void**)&k, g_k);
    cudaGetSymbolAddress((void**)&v, g_v);
    cudaGetSymbolAddress((void**)&o, g_o);
    cudaGetSymbolAddress((void**)&u, g_u);

    embed_kernel<<<NTOK, 256>>>(idx, tok, pos, x);

    dim3 gE(EMB / BN, NTOK / BM);      // 8 x 32
    dim3 gH(HID / BN, NTOK / BM);      // 32 x 32
    dim3 gV(VOCAB / BN, NTOK / BM);    // 250 x 32
    dim3 gA(SEQ, 2 * NH);              // 2048 x 32

    for (int l = 0; l < NL; l++) {
        const float* wq = Wq + (size_t)l * EMB * EMB;
        const float* wk = Wk + (size_t)l * EMB * EMB;
        const float* wv = Wv + (size_t)l * EMB * EMB;
        const float* wp = Wp + (size_t)l * EMB * EMB;
        const float* w1 = W1 + (size_t)l * EMB * HID;
        const float* w2 = W2 + (size_t)l * HID * EMB;

        ln_kernel<<<NTOK, 256>>>(x, ln1_g + l * EMB, ln1_b + l * EMB, h);
        sgemm_kernel<<<gE, 256>>>(h, wq, nullptr, nullptr, q, NTOK, EMB, EMB, 0);
        sgemm_kernel<<<gE, 256>>>(h, wk, nullptr, nullptr, k, NTOK, EMB, EMB, 0);
        sgemm_kernel<<<gE, 256>>>(h, wv, nullptr, nullptr, v, NTOK, EMB, EMB, 0);
        attn_kernel<<<gA, 128>>>(q, k, v, o);
        sgemm_kernel<<<gE, 256>>>(o, wp, bp + l * EMB, x, x, NTOK, EMB, EMB,
                                  FLAG_BIAS | FLAG_RES);
        ln_kernel<<<NTOK, 256>>>(x, ln2_g + l * EMB, ln2_b + l * EMB, h);
        sgemm_kernel<<<gH, 256>>>(h, w1, b1 + l * HID, nullptr, u, NTOK, HID, EMB,
                                  FLAG_BIAS | FLAG_GELU);
        sgemm_kernel<<<gE, 256>>>(u, w2, b2 + l * EMB, x, x, NTOK, EMB, HID,
                                  FLAG_BIAS | FLAG_RES);
    }

    ln_kernel<<<NTOK, 256>>>(x, lnf_g, lnf_b, h);
    sgemm_kernel<<<gV, 256>>>(h, Wout, nullptr, nullptr, (float*)d_out,
                              NTOK, VOCAB, EMB, 0);
}

// round 4
// speedup vs baseline: 2.6044x; 2.5984x over previous
#include <cuda_runtime.h>
#include <cuda_bf16.h>
#include <math.h>
#include <stdint.h>

#define NTOK 4096
#define EMB  1024
#define HID  4096
#define VOCAB 32000
#define SEQ  2048
#define NH   16
#define HD   64
#define NL   8

__device__ float g_x[NTOK * EMB];
__device__ float g_h[NTOK * EMB];
__device__ float g_q[NTOK * EMB];
__device__ float g_k[NTOK * EMB];
__device__ float g_v[NTOK * EMB];
__device__ float g_o[NTOK * EMB];
__device__ float g_u[NTOK * HID];

__device__ __forceinline__ uint32_t smem_u32(const void* p) {
    return (uint32_t)__cvta_generic_to_shared((void*)p);
}
__device__ __forceinline__ uint32_t pack_bf2(float a, float b) {
    __nv_bfloat162 t = __floats2bfloat162_rn(a, b);
    return *reinterpret_cast<uint32_t*>(&t);
}

#define LDSM4(r, a) \
    asm volatile("ldmatrix.sync.aligned.m8n8.x4.shared.b16 {%0,%1,%2,%3}, [%4];" \
        : "=r"((r)[0]), "=r"((r)[1]), "=r"((r)[2]), "=r"((r)[3]) : "r"(a))

#define MMA16816(d, a, b) \
    asm volatile("mma.sync.aligned.m16n8k16.row.col.f32.bf16.bf16.f32 " \
        "{%0,%1,%2,%3},{%4,%5,%6,%7},{%8,%9},{%0,%1,%2,%3};" \
        : "+f"((d)[0]), "+f"((d)[1]), "+f"((d)[2]), "+f"((d)[3]) \
        : "r"((a)[0]), "r"((a)[1]), "r"((a)[2]), "r"((a)[3]), \
          "r"((b)[0]), "r"((b)[1]))

// ---------------- embed ------------------------------------------------------
__global__ void embed_kernel(const int* __restrict__ idx, const float* __restrict__ tok,
                             const float* __restrict__ pos, float* __restrict__ x) {
    int n = blockIdx.x, e4 = threadIdx.x, t = n & (SEQ - 1);
    float4 a = ((const float4*)(tok + (size_t)idx[n] * EMB))[e4];
    float4 b = ((const float4*)(pos + (size_t)t * EMB))[e4];
    a.x += b.x; a.y += b.y; a.z += b.z; a.w += b.w;
    ((float4*)(x + (size_t)n * EMB))[e4] = a;
}

// ---------------- layernorm --------------------------------------------------
__device__ __forceinline__ float block_sum_256(float s, float* red) {
    #pragma unroll
    for (int o = 16; o; o >>= 1) s += __shfl_xor_sync(0xffffffffu, s, o);
    if ((threadIdx.x & 31) == 0) red[threadIdx.x >> 5] = s;
    __syncthreads();
    if (threadIdx.x < 32) {
        float t = (threadIdx.x < 8) ? red[threadIdx.x] : 0.0f;
        #pragma unroll
        for (int o = 4; o; o >>= 1) t += __shfl_xor_sync(0xffffffffu, t, o);
        if (threadIdx.x == 0) red[0] = t;
    }
    __syncthreads();
    float r = red[0];
    __syncthreads();
    return r;
}

__global__ void ln_kernel(const float* __restrict__ x, const float* __restrict__ g,
                          const float* __restrict__ b, float* __restrict__ out) {
    __shared__ float red[8];
    int n = blockIdx.x, tid = threadIdx.x;
    float4 v = ((const float4*)(x + (size_t)n * EMB))[tid];
    float mu = block_sum_256(v.x + v.y + v.z + v.w, red) * (1.0f / EMB);
    float dx = v.x - mu, dy = v.y - mu, dz = v.z - mu, dw = v.w - mu;
    float var = block_sum_256(dx*dx + dy*dy + dz*dz + dw*dw, red) * (1.0f / EMB);
    float rs = rsqrtf(var + 1e-5f);
    float4 gg = ((const float4*)g)[tid];
    float4 bb = ((const float4*)b)[tid];
    float4 r;
    r.x = dx*rs*gg.x + bb.x; r.y = dy*rs*gg.y + bb.y;
    r.z = dz*rs*gg.z + bb.z; r.w = dw*rs*gg.w + bb.w;
    ((float4*)(out + (size_t)n * EMB))[tid] = r;
}

// =================== mma.sync split-bf16 GEMM ================================
// C[M,N] = op(A[M,K] @ B[K,N] [+bias]) [+res].
// 128x128 CTA tile, BK=32, 8 warps (2x4), warp tile 64x32.
// smem tiles: [128 rows][128B] = hi bf16[32] | lo bf16[32], chunk-swizzled.
#define FLAG_BIAS 1
#define FLAG_GELU 2
#define FLAG_RES  4
#define MG_SMEM (2 * 32768)

__global__ __launch_bounds__(256, 1) void mgemm_kernel(
    const float* __restrict__ A, const float* __restrict__ B,
    const float* __restrict__ bias, const float* __restrict__ res,
    float* __restrict__ C, int M, int N, int K, int flags) {
    extern __shared__ char sm[];
    uint32_t smb = smem_u32(sm);

    int tid = threadIdx.x;
    int lane = tid & 31, wid = tid >> 5;
    int warp_m = wid >> 2, warp_n = wid & 3;      // 2 x 4 warps
    int rowBase = blockIdx.y * 128, colBase = blockIdx.x * 128;

    const float* Ag = A + (size_t)rowBase * K;
    const float* Bg = B + colBase;

    float acc[4][4][4];
    #pragma unroll
    for (int i = 0; i < 4; i++)
        #pragma unroll
        for (int j = 0; j < 4; j++)
            #pragma unroll
            for (int q = 0; q < 4; q++) acc[i][j][q] = 0.0f;

    float4 pfA[4];
    float  pfB[16];

    int S = K >> 5;   // stages of BK=32

    // ---- prologue: load stage 0 ----
    #pragma unroll
    for (int i = 0; i < 4; i++) {
        int u = tid + i * 256;
        int r = u >> 3, c4 = u & 7;
        pfA[i] = *(const float4*)(Ag + (size_t)r * K + c4 * 4);
    }
    #pragma unroll
    for (int i = 0; i < 4; i++) {
        int g = tid + i * 256;
        int n = g & 127, k4 = g >> 7;
        const float* bp = Bg + (size_t)(k4 * 4) * N + n;
        pfB[i*4+0] = bp[0]; pfB[i*4+1] = bp[(size_t)N];
        pfB[i*4+2] = bp[2*(size_t)N]; pfB[i*4+3] = bp[3*(size_t)N];
    }

    for (int s = 0; s < S; ++s) {
        int buf = s & 1;
        char* Asm = sm + buf * 32768;
        char* Bsm = Asm + 16384;

        // store prefetched tile (convert fp32 -> hi/lo bf16)
        #pragma unroll
        for (int i = 0; i < 4; i++) {
            int u = tid + i * 256;
            int r = u >> 3, c4 = u & 7;
            float4 v = pfA[i];
            float hx = __bfloat162float(__float2bfloat16(v.x));
            float hy = __bfloat162float(__float2bfloat16(v.y));
            float hz = __bfloat162float(__float2bfloat16(v.z));
            float hw = __bfloat162float(__float2bfloat16(v.w));
            int ch = (c4 >> 1), sub = (c4 & 1) * 8;
            *(uint2*)(Asm + r*128 + ((ch ^ (r & 7)) * 16) + sub) =
                make_uint2(pack_bf2(v.x, v.y), pack_bf2(v.z, v.w));
            *(uint2*)(Asm + r*128 + (((ch + 4) ^ (r & 7)) * 16) + sub) =
                make_uint2(pack_bf2(v.x - hx, v.y - hy), pack_bf2(v.z - hz, v.w - hw));
        }
        #pragma unroll
        for (int i = 0; i < 4; i++) {
            int g = tid + i * 256;
            int n = g & 127, k4 = g >> 7;
            float b0 = pfB[i*4+0], b1 = pfB[i*4+1], b2 = pfB[i*4+2], b3 = pfB[i*4+3];
            float h0 = __bfloat162float(__float2bfloat16(b0));
            float h1 = __bfloat162float(__float2bfloat16(b1));
            float h2 = __bfloat162float(__float2bfloat16(b2));
            float h3 = __bfloat162float(__float2bfloat16(b3));
            int ch = (k4 >> 1), sub = (k4 & 1) * 8;
            *(uint2*)(Bsm + n*128 + ((ch ^ (n & 7)) * 16) + sub) =
                make_uint2(pack_bf2(b0, b1), pack_bf2(b2, b3));
            *(uint2*)(Bsm + n*128 + (((ch + 4) ^ (n & 7)) * 16) + sub) =
                make_uint2(pack_bf2(b0 - h0, b1 - h1), pack_bf2(b2 - h2, b3 - h3));
        }
        __syncthreads();

        // prefetch next stage while computing
        if (s + 1 < S) {
            int k0 = (s + 1) * 32;
            #pragma unroll
            for (int i = 0; i < 4; i++) {
                int u = tid + i * 256;
                int r = u >> 3, c4 = u & 7;
                pfA[i] = *(const float4*)(Ag + (size_t)r * K + k0 + c4 * 4);
            }
            #pragma unroll
            for (int i = 0; i < 4; i++) {
                int g = tid + i * 256;
                int n = g & 127, k4 = g >> 7;
                const float* bp = Bg + (size_t)(k0 + k4 * 4) * N + n;
                pfB[i*4+0] = bp[0]; pfB[i*4+1] = bp[(size_t)N];
                pfB[i*4+2] = bp[2*(size_t)N]; pfB[i*4+3] = bp[3*(size_t)N];
            }
        }

        uint32_t Asmb = smb + buf * 32768;
        uint32_t Bsmb = Asmb + 16384;
        #pragma unroll
        for (int kk = 0; kk < 2; ++kk) {
            uint32_t ah[4][4], al[4][4];
            #pragma unroll
            for (int mt = 0; mt < 4; ++mt) {
                int r = warp_m * 64 + mt * 16 + (lane & 15);
                int ch = kk * 2 + (lane >> 4);
                LDSM4(ah[mt], Asmb + r * 128 + ((ch ^ (r & 7)) * 16));
                LDSM4(al[mt], Asmb + r * 128 + (((ch + 4) ^ (r & 7)) * 16));
            }
            uint32_t bh[8], bl[8];
            #pragma unroll
            for (int g2 = 0; g2 < 2; ++g2) {
                int n = warp_n * 32 + g2 * 16 + ((lane >> 4) << 3) + (lane & 7);
                int ch = kk * 2 + ((lane >> 3) & 1);
                LDSM4(&bh[g2 * 4], Bsmb + n * 128 + ((ch ^ (n & 7)) * 16));
                LDSM4(&bl[g2 * 4], Bsmb + n * 128 + (((ch + 4) ^ (n & 7)) * 16));
            }
            #pragma unroll
            for (int mt = 0; mt < 4; ++mt)
                #pragma unroll
                for (int nt = 0; nt < 4; ++nt) {
                    uint32_t* ph = &bh[(nt >> 1) * 4 + (nt & 1) * 2];
                    uint32_t* pl = &bl[(nt >> 1) * 4 + (nt & 1) * 2];
                    MMA16816(acc[mt][nt], ah[mt], ph);
                    MMA16816(acc[mt][nt], ah[mt], pl);
                    MMA16816(acc[mt][nt], al[mt], ph);
                }
        }
        __syncthreads();
    }

    // ---- epilogue ----
    #pragma unroll
    for (int mt = 0; mt < 4; ++mt) {
        #pragma unroll
        for (int nt = 0; nt < 4; ++nt) {
            int col = colBase + warp_n * 32 + nt * 8 + (lane & 3) * 2;
            int row0 = rowBase + warp_m * 64 + mt * 16 + (lane >> 2);
            #pragma unroll
            for (int half = 0; half < 2; ++half) {
                size_t row = (size_t)(row0 + half * 8);
                float v0 = acc[mt][nt][half * 2 + 0];
                float v1 = acc[mt][nt][half * 2 + 1];
                if (flags & FLAG_BIAS) { v0 += bias[col]; v1 += bias[col + 1]; }
                if (flags & FLAG_GELU) {
                    v0 = 0.5f * v0 * (1.0f + erff(v0 * 0.70710678118654752f));
                    v1 = 0.5f * v1 * (1.0f + erff(v1 * 0.70710678118654752f));
                }
                if (flags & FLAG_RES) {
                    float2 rv = *(const float2*)(res + row * N + col);
                    v0 += rv.x; v1 += rv.y;
                }
                *(float2*)(C + row * N + col) = make_float2(v0, v1);
            }
        }
    }
}

// =================== flash attention (64-query tiles, fp32) ==================
#define FA_SMEM (3 * 64 * 68 * 4 + 64 * 65 * 4)

__global__ __launch_bounds__(128) void fattn_kernel(
    const float* __restrict__ q, const float* __restrict__ k,
    const float* __restrict__ v, float* __restrict__ o) {
    extern __shared__ float smf[];
    float* Qs = smf;
    float* Ks = smf + 64 * 68;
    float* Vs = smf + 2 * 64 * 68;
    float* Ss = smf + 3 * 64 * 68;     // 64 x 65

    int qt = blockIdx.x;
    int bh = blockIdx.y;
    int b = bh >> 4, h = bh & 15;
    size_t base = (size_t)(b * SEQ) * EMB + h * HD;
    int qBase = qt * 64;
    int tid = threadIdx.x;
    int r = tid >> 1, hf = tid & 1;

    #pragma unroll
    for (int j = 0; j < 8; ++j) {
        int f = tid + j * 128;
        int rr = f >> 4, d4 = f & 15;
        *(float4*)(Qs + rr * 68 + d4 * 4) =
            *(const float4*)(q + base + (size_t)(qBase + rr) * EMB + d4 * 4);
    }

    float m = -1e30f, l = 0.0f;
    float acc[32];
    #pragma unroll
    for (int i = 0; i < 32; ++i) acc[i] = 0.0f;

    for (int kt = 0; kt <= qt; ++kt) {
        int kBase = kt * 64;
        __syncthreads();
        #pragma unroll
        for (int j = 0; j < 8; ++j) {
            int f = tid + j * 128;
            int rr = f >> 4, d4 = f & 15;
            *(float4*)(Ks + rr * 68 + d4 * 4) =
                *(const float4*)(k + base + (size_t)(kBase + rr) * EMB + d4 * 4);
            *(float4*)(Vs + rr * 68 + d4 * 4) =
                *(const float4*)(v + base + (size_t)(kBase + rr) * EMB + d4 * 4);
        }
        __syncthreads();

        float s[32];
        #pragma unroll
        for (int c = 0; c < 32; ++c) s[c] = 0.0f;
        for (int d = 0; d < 64; ++d) {
            float qv = Qs[r * 68 + d];
            #pragma unroll
            for (int c = 0; c < 32; ++c)
                s[c] = fmaf(qv, Ks[(hf * 32 + c) * 68 + d], s[c]);
        }
        int rglob = qBase + r;
        float rowmax = -1e30f;
        #pragma unroll
        for (int c = 0; c < 32; ++c) {
            int cg = kBase + hf * 32 + c;
            s[c] = (cg <= rglob) ? s[c] * 0.125f : -1e30f;
            rowmax = fmaxf(rowmax, s[c]);
        }
        rowmax = fmaxf(rowmax, __shfl_xor_sync(0xffffffffu, rowmax, 1));
        float mnew = fmaxf(m, rowmax);
        float corr = __expf(m - mnew);
        float psum = 0.0f;
        #pragma unroll
        for (int c = 0; c < 32; ++c) {
            float p = __expf(s[c] - mnew);
            Ss[r * 65 + hf * 32 + c] = p;
            psum += p;
        }
        psum += __shfl_xor_sync(0xffffffffu, psum, 1);
        l = l * corr + psum;
        m = mnew;
        #pragma unroll
        for (int i = 0; i < 32; ++i) acc[i] *= corr;
        __syncthreads();
        for (int c = 0; c < 64; ++c) {
            float p = Ss[r * 65 + c];
            #pragma unroll
            for (int i = 0; i < 32; ++i)
                acc[i] = fmaf(p, Vs[c * 68 + hf * 32 + i], acc[i]);
        }
    }
    float inv = 1.0f / l;
    float* orow = o + base + (size_t)(qBase + r) * EMB + hf * 32;
    #pragma unroll
    for (int i = 0; i < 32; i += 4)
        *(float4*)(orow + i) = make_float4(acc[i]*inv, acc[i+1]*inv, acc[i+2]*inv, acc[i+3]*inv);
}

// ---------------- launch ----------------------------------------------------
extern "C" void kernel_launch(void* const* d_in, const int* in_sizes, int n_in,
                              void* d_out, int out_size) {
    const int*   idx    = (const int*)d_in[0];
    const float* tok    = (const float*)d_in[1];
    const float* pos    = (const float*)d_in[2];
    const float* Wq     = (const float*)d_in[3];
    const float* Wk     = (const float*)d_in[4];
    const float* Wv     = (const float*)d_in[5];
    const float* Wp     = (const float*)d_in[6];
    const float* bp     = (const float*)d_in[7];
    const float* ln1_g  = (const float*)d_in[8];
    const float* ln1_b  = (const float*)d_in[9];
    const float* ln2_g  = (const float*)d_in[10];
    const float* ln2_b  = (const float*)d_in[11];
    const float* W1     = (const float*)d_in[12];
    const float* b1     = (const float*)d_in[13];
    const float* W2     = (const float*)d_in[14];
    const float* b2     = (const float*)d_in[15];
    const float* lnf_g  = (const float*)d_in[16];
    const float* lnf_b  = (const float*)d_in[17];
    const float* Wout   = (const float*)d_in[18];

    float *x, *h, *q, *k, *v, *o, *u;
    cudaGetSymbolAddress((void**)&x, g_x);
    cudaGetSymbolAddress((void**)&h, g_h);
    cudaGetSymbolAddress((void**)&q, g_q);
    cudaGetSymbolAddress((void**)&k, g_k);
    cudaGetSymbolAddress((void**)&v, g_v);
    cudaGetSymbolAddress((void**)&o, g_o);
    cudaGetSymbolAddress((void**)&u, g_u);

    cudaFuncSetAttribute(mgemm_kernel, cudaFuncAttributeMaxDynamicSharedMemorySize, MG_SMEM);
    cudaFuncSetAttribute(fattn_kernel, cudaFuncAttributeMaxDynamicSharedMemorySize, FA_SMEM);

    embed_kernel<<<NTOK, 256>>>(idx, tok, pos, x);

    dim3 gE(EMB / 128, NTOK / 128);     // 8 x 32
    dim3 gH(HID / 128, NTOK / 128);     // 32 x 32
    dim3 gV(VOCAB / 128, NTOK / 128);   // 250 x 32
    dim3 gA(SEQ / 64, 2 * NH);          // 32 x 32

    for (int l = 0; l < NL; l++) {
        const float* wq = Wq + (size_t)l * EMB * EMB;
        const float* wk = Wk + (size_t)l * EMB * EMB;
        const float* wv = Wv + (size_t)l * EMB * EMB;
        const float* wp = Wp + (size_t)l * EMB * EMB;
        const float* w1 = W1 + (size_t)l * EMB * HID;
        const float* w2 = W2 + (size_t)l * HID * EMB;

        ln_kernel<<<NTOK, 256>>>(x, ln1_g + l * EMB, ln1_b + l * EMB, h);
        mgemm_kernel<<<gE, 256, MG_SMEM>>>(h, wq, nullptr, nullptr, q, NTOK, EMB, EMB, 0);
        mgemm_kernel<<<gE, 256, MG_SMEM>>>(h, wk, nullptr, nullptr, k, NTOK, EMB, EMB, 0);
        mgemm_kernel<<<gE, 256, MG_SMEM>>>(h, wv, nullptr, nullptr, v, NTOK, EMB, EMB, 0);
        fattn_kernel<<<gA, 128, FA_SMEM>>>(q, k, v, o);
        mgemm_kernel<<<gE, 256, MG_SMEM>>>(o, wp, bp + l * EMB, x, x, NTOK, EMB, EMB,
                                           FLAG_BIAS | FLAG_RES);
        ln_kernel<<<NTOK, 256>>>(x, ln2_g + l * EMB, ln2_b + l * EMB, h);
        mgemm_kernel<<<gH, 256, MG_SMEM>>>(h, w1, b1 + l * HID, nullptr, u, NTOK, HID, EMB,
                                           FLAG_BIAS | FLAG_GELU);
        mgemm_kernel<<<gE, 256, MG_SMEM>>>(u, w2, b2 + l * EMB, x, x, NTOK, EMB, HID,
                                           FLAG_BIAS | FLAG_RES);
    }

    ln_kernel<<<NTOK, 256>>>(x, lnf_g, lnf_b, h);
    mgemm_kernel<<<gV, 256, MG_SMEM>>>(h, Wout, nullptr, nullptr, (float*)d_out,
                                       NTOK, VOCAB, EMB, 0);
}

// round 5
// speedup vs baseline: 3.0693x; 1.1785x over previous
#include <cuda_runtime.h>
#include <cuda_bf16.h>
#include <math.h>
#include <stdint.h>

#define NTOK 4096
#define EMB  1024
#define HID  4096
#define VOCAB 32000
#define SEQ  2048
#define NH   16
#define HD   64
#define NL   8

typedef __nv_bfloat16 bf16;
typedef __nv_bfloat162 bf162;

// ---------------- device scratch --------------------------------------------
__device__ __align__(16) float g_x[NTOK * EMB];
__device__ __align__(16) float g_q[NTOK * EMB];
__device__ __align__(16) float g_k[NTOK * EMB];
__device__ __align__(16) float g_v[NTOK * EMB];

__device__ __align__(16) bf16 g_h_h[NTOK * EMB];
__device__ __align__(16) bf16 g_h_l[NTOK * EMB];
__device__ __align__(16) bf16 g_o_h[NTOK * EMB];
__device__ __align__(16) bf16 g_o_l[NTOK * EMB];
__device__ __align__(16) bf16 g_u_h[NTOK * HID];
__device__ __align__(16) bf16 g_u_l[NTOK * HID];

// transposed weights [N][K] hi/lo
__device__ __align__(16) bf16 g_Wq_h[NL * EMB * EMB];
__device__ __align__(16) bf16 g_Wq_l[NL * EMB * EMB];
__device__ __align__(16) bf16 g_Wk_h[NL * EMB * EMB];
__device__ __align__(16) bf16 g_Wk_l[NL * EMB * EMB];
__device__ __align__(16) bf16 g_Wv_h[NL * EMB * EMB];
__device__ __align__(16) bf16 g_Wv_l[NL * EMB * EMB];
__device__ __align__(16) bf16 g_Wp_h[NL * EMB * EMB];
__device__ __align__(16) bf16 g_Wp_l[NL * EMB * EMB];
__device__ __align__(16) bf16 g_W1_h[NL * EMB * HID];
__device__ __align__(16) bf16 g_W1_l[NL * EMB * HID];
__device__ __align__(16) bf16 g_W2_h[NL * EMB * HID];
__device__ __align__(16) bf16 g_W2_l[NL * EMB * HID];
__device__ __align__(16) bf16 g_Wo_h[(size_t)VOCAB * EMB];
__device__ __align__(16) bf16 g_Wo_l[(size_t)VOCAB * EMB];

// ---------------- helpers ---------------------------------------------------
__device__ __forceinline__ uint32_t smem_u32(const void* p) {
    return (uint32_t)__cvta_generic_to_shared((void*)p);
}
__device__ __forceinline__ uint32_t pack_bf2(float a, float b) {
    bf162 t = __floats2bfloat162_rn(a, b);
    return *reinterpret_cast<uint32_t*>(&t);
}
__device__ __forceinline__ void cpa16(uint32_t dst, const void* src) {
    asm volatile("cp.async.ca.shared.global [%0], [%1], 16;" :: "r"(dst), "l"(src));
}
#define CPA_COMMIT() asm volatile("cp.async.commit_group;" ::: "memory")
#define CPA_WAIT0()  asm volatile("cp.async.wait_group 0;" ::: "memory")

#define LDSM4(r, a) \
    asm volatile("ldmatrix.sync.aligned.m8n8.x4.shared.b16 {%0,%1,%2,%3}, [%4];" \
        : "=r"((r)[0]), "=r"((r)[1]), "=r"((r)[2]), "=r"((r)[3]) : "r"(a))

#define MMA16816(d, a, b) \
    asm volatile("mma.sync.aligned.m16n8k16.row.col.f32.bf16.bf16.f32 " \
        "{%0,%1,%2,%3},{%4,%5,%6,%7},{%8,%9},{%0,%1,%2,%3};" \
        : "+f"((d)[0]), "+f"((d)[1]), "+f"((d)[2]), "+f"((d)[3]) \
        : "r"((a)[0]), "r"((a)[1]), "r"((a)[2]), "r"((a)[3]), \
          "r"((b)[0]), "r"((b)[1]))

// ---------------- weight transpose + split-convert ---------------------------
// in: [K][N] fp32 (layer z), out: [N][K] hi/lo bf16
__global__ void tconv_kernel(const float* __restrict__ in, bf16* __restrict__ oh,
                             bf16* __restrict__ ol, int K, int N) {
    __shared__ float t[32][33];
    size_t zoff = (size_t)blockIdx.z * K * N;
    const float* I = in + zoff;
    bf16* OH = oh + zoff;
    bf16* OL = ol + zoff;
    int bx = blockIdx.x * 32;   // N
    int by = blockIdx.y * 32;   // K
    int x = threadIdx.x, y = threadIdx.y;
    #pragma unroll
    for (int i = 0; i < 4; i++)
        t[y + i * 8][x] = I[(size_t)(by + y + i * 8) * N + bx + x];
    __syncthreads();
    #pragma unroll
    for (int i = 0; i < 4; i++) {
        int n = bx + y + i * 8, k = by + x;
        float v = t[x][y + i * 8];
        bf16 hv = __float2bfloat16(v);
        OH[(size_t)n * K + k] = hv;
        OL[(size_t)n * K + k] = __float2bfloat16(v - __bfloat162float(hv));
    }
}

// ---------------- embed ------------------------------------------------------
__global__ void embed_kernel(const int* __restrict__ idx, const float* __restrict__ tok,
                             const float* __restrict__ pos, float* __restrict__ x) {
    int n = blockIdx.x, e4 = threadIdx.x, t = n & (SEQ - 1);
    float4 a = ((const float4*)(tok + (size_t)idx[n] * EMB))[e4];
    float4 b = ((const float4*)(pos + (size_t)t * EMB))[e4];
    a.x += b.x; a.y += b.y; a.z += b.z; a.w += b.w;
    ((float4*)(x + (size_t)n * EMB))[e4] = a;
}

// ---------------- layernorm -> hi/lo bf16 ------------------------------------
__device__ __forceinline__ float block_sum_256(float s, float* red) {
    #pragma unroll
    for (int o = 16; o; o >>= 1) s += __shfl_xor_sync(0xffffffffu, s, o);
    if ((threadIdx.x & 31) == 0) red[threadIdx.x >> 5] = s;
    __syncthreads();
    if (threadIdx.x < 32) {
        float t = (threadIdx.x < 8) ? red[threadIdx.x] : 0.0f;
        #pragma unroll
        for (int o = 4; o; o >>= 1) t += __shfl_xor_sync(0xffffffffu, t, o);
        if (threadIdx.x == 0) red[0] = t;
    }
    __syncthreads();
    float r = red[0];
    __syncthreads();
    return r;
}

__global__ void ln_kernel(const float* __restrict__ x, const float* __restrict__ g,
                          const float* __restrict__ b, bf16* __restrict__ oh,
                          bf16* __restrict__ ol) {
    __shared__ float red[8];
    int n = blockIdx.x, tid = threadIdx.x;
    float4 v = ((const float4*)(x + (size_t)n * EMB))[tid];
    float mu = block_sum_256(v.x + v.y + v.z + v.w, red) * (1.0f / EMB);
    float dx = v.x - mu, dy = v.y - mu, dz = v.z - mu, dw = v.w - mu;
    float var = block_sum_256(dx*dx + dy*dy + dz*dz + dw*dw, red) * (1.0f / EMB);
    float rs = rsqrtf(var + 1e-5f);
    float4 gg = ((const float4*)g)[tid];
    float4 bb = ((const float4*)b)[tid];
    float r0 = dx*rs*gg.x + bb.x, r1 = dy*rs*gg.y + bb.y;
    float r2 = dz*rs*gg.z + bb.z, r3 = dw*rs*gg.w + bb.w;
    float h0 = __bfloat162float(__float2bfloat16(r0));
    float h1 = __bfloat162float(__float2bfloat16(r1));
    float h2 = __bfloat162float(__float2bfloat16(r2));
    float h3 = __bfloat162float(__float2bfloat16(r3));
    size_t o = (size_t)n * EMB + tid * 4;
    *(uint2*)(oh + o) = make_uint2(pack_bf2(r0, r1), pack_bf2(r2, r3));
    *(uint2*)(ol + o) = make_uint2(pack_bf2(r0 - h0, r1 - h1), pack_bf2(r2 - h2, r3 - h3));
}

// =================== cp.async split-bf16 MMA GEMM ============================
// A: hi/lo bf16 [M][K], B: hi/lo bf16 [N][K] (pre-transposed).
// 128x128 CTA tile, BK=64, 8 warps (2x4), warp 64x32, double-buffered cp.async.
#define FLAG_BIAS 1
#define FLAG_GELU 2
#define FLAG_RES  4
#define FLAG_OSPL 8
#define MG_SMEM (2 * 65536)

__global__ __launch_bounds__(256, 1) void mgemm2_kernel(
    const bf16* __restrict__ Ah, const bf16* __restrict__ Al,
    const bf16* __restrict__ Bh, const bf16* __restrict__ Bl,
    const float* __restrict__ bias, const float* __restrict__ res,
    float* __restrict__ C, bf16* __restrict__ Oh, bf16* __restrict__ Ol,
    int M, int N, int K, int flags) {
    extern __shared__ char sm[];
    uint32_t smb = smem_u32(sm);

    int tid = threadIdx.x;
    int lane = tid & 31, wid = tid >> 5;
    int warp_m = wid >> 2, warp_n = wid & 3;
    int rowBase = blockIdx.x * 128, colBase = blockIdx.y * 128;

    float acc[4][4][4];
    #pragma unroll
    for (int i = 0; i < 4; i++)
        #pragma unroll
        for (int j = 0; j < 4; j++)
            #pragma unroll
            for (int q = 0; q < 4; q++) acc[i][j][q] = 0.0f;

    int S = K >> 6;

    // per-thread chunk coords (4 chunks per operand array per stage)
    int r0 = tid >> 3, c0 = tid & 7;     // +32 rows per i

    // ---- issue loads for a stage ----
    auto load_stage = [&](int s, int buf) {
        uint32_t sb = smb + buf * 65536;
        const bf16* gA_h = Ah + (size_t)rowBase * K + s * 64;
        const bf16* gA_l = Al + (size_t)rowBase * K + s * 64;
        const bf16* gB_h = Bh + (size_t)colBase * K + s * 64;
        const bf16* gB_l = Bl + (size_t)colBase * K + s * 64;
        #pragma unroll
        for (int i = 0; i < 4; i++) {
            int r = r0 + i * 32;
            uint32_t so = (uint32_t)(r * 128 + ((c0 ^ (r & 7)) * 16));
            size_t go = (size_t)r * K + c0 * 8;
            cpa16(sb + so,         gA_h + go);
            cpa16(sb + 16384 + so, gA_l + go);
            cpa16(sb + 32768 + so, gB_h + go);
            cpa16(sb + 49152 + so, gB_l + go);
        }
        CPA_COMMIT();
    };

    load_stage(0, 0);

    for (int s = 0; s < S; ++s) {
        int buf = s & 1;
        CPA_WAIT0();
        __syncthreads();
        if (s + 1 < S) load_stage(s + 1, buf ^ 1);

        uint32_t AsH = smb + buf * 65536;
        uint32_t AsL = AsH + 16384;
        uint32_t BsH = AsH + 32768;
        uint32_t BsL = AsH + 49152;

        #pragma unroll
        for (int kk = 0; kk < 4; ++kk) {
            uint32_t ah[4][4], al[4][4];
            #pragma unroll
            for (int mt = 0; mt < 4; ++mt) {
                int r = warp_m * 64 + mt * 16 + (lane & 15);
                int ch = kk * 2 + (lane >> 4);
                uint32_t off = (uint32_t)(r * 128 + ((ch ^ (r & 7)) * 16));
                LDSM4(ah[mt], AsH + off);
                LDSM4(al[mt], AsL + off);
            }
            uint32_t bh[8], bl[8];
            #pragma unroll
            for (int g2 = 0; g2 < 2; ++g2) {
                int n = warp_n * 32 + g2 * 16 + ((lane >> 4) << 3) + (lane & 7);
                int ch = kk * 2 + ((lane >> 3) & 1);
                uint32_t off = (uint32_t)(n * 128 + ((ch ^ (n & 7)) * 16));
                LDSM4(&bh[g2 * 4], BsH + off);
                LDSM4(&bl[g2 * 4], BsL + off);
            }
            #pragma unroll
            for (int mt = 0; mt < 4; ++mt)
                #pragma unroll
                for (int nt = 0; nt < 4; ++nt) {
                    uint32_t* ph = &bh[(nt >> 1) * 4 + (nt & 1) * 2];
                    uint32_t* pl = &bl[(nt >> 1) * 4 + (nt & 1) * 2];
                    MMA16816(acc[mt][nt], ah[mt], ph);
                    MMA16816(acc[mt][nt], ah[mt], pl);
                    MMA16816(acc[mt][nt], al[mt], ph);
                }
        }
        __syncthreads();
    }

    // ---- epilogue ----
    #pragma unroll
    for (int mt = 0; mt < 4; ++mt) {
        #pragma unroll
        for (int nt = 0; nt < 4; ++nt) {
            int col = colBase + warp_n * 32 + nt * 8 + (lane & 3) * 2;
            int row0 = rowBase + warp_m * 64 + mt * 16 + (lane >> 2);
            #pragma unroll
            for (int half = 0; half < 2; ++half) {
                size_t row = (size_t)(row0 + half * 8);
                float v0 = acc[mt][nt][half * 2 + 0];
                float v1 = acc[mt][nt][half * 2 + 1];
                if (flags & FLAG_BIAS) { v0 += bias[col]; v1 += bias[col + 1]; }
                if (flags & FLAG_GELU) {
                    v0 = 0.5f * v0 * (1.0f + erff(v0 * 0.70710678118654752f));
                    v1 = 0.5f * v1 * (1.0f + erff(v1 * 0.70710678118654752f));
                }
                if (flags & FLAG_RES) {
                    float2 rv = *(const float2*)(res + row * N + col);
                    v0 += rv.x; v1 += rv.y;
                }
                if (flags & FLAG_OSPL) {
                    float h0 = __bfloat162float(__float2bfloat16(v0));
                    float h1 = __bfloat162float(__float2bfloat16(v1));
                    *(uint32_t*)(Oh + row * N + col) = pack_bf2(v0, v1);
                    *(uint32_t*)(Ol + row * N + col) = pack_bf2(v0 - h0, v1 - h1);
                } else {
                    *(float2*)(C + row * N + col) = make_float2(v0, v1);
                }
            }
        }
    }
}

// =================== flash attention v2 (register-tiled fp32) ================
// Block: 64 queries x (b,h). 128 threads: ty=tid>>3 owns rows {ty+16i}, tx=tid&7
// owns 8 cols (score: k-cols; PV: d-cols). Output written as hi/lo bf16.
#define FA_SMEM (4 * 64 * 68 * 4)

__global__ __launch_bounds__(128) void fattn_kernel(
    const float* __restrict__ qg, const float* __restrict__ kg,
    const float* __restrict__ vg, bf16* __restrict__ oh, bf16* __restrict__ ol) {
    extern __shared__ float smf[];
    float* Qs = smf;
    float* Ks = smf + 64 * 68;
    float* Vs = smf + 2 * 64 * 68;
    float* Ps = smf + 3 * 64 * 68;

    int qt = blockIdx.x;
    int bh = blockIdx.y;
    int b = bh >> 4, h = bh & 15;
    size_t base = (size_t)(b * SEQ) * EMB + h * HD;
    int qBase = qt * 64;
    int tid = threadIdx.x;
    int ty = tid >> 3, tx = tid & 7;

    // load Q tile [64][64] -> Qs stride 68
    #pragma unroll
    for (int j = 0; j < 8; ++j) {
        int f = tid + j * 128;
        int rr = f >> 4, d4 = f & 15;
        *(float4*)(Qs + rr * 68 + d4 * 4) =
            *(const float4*)(qg + base + (size_t)(qBase + rr) * EMB + d4 * 4);
    }

    float m[4], l[4], acc[4][8];
    #pragma unroll
    for (int i = 0; i < 4; ++i) {
        m[i] = -1e30f; l[i] = 0.0f;
        #pragma unroll
        for (int j = 0; j < 8; ++j) acc[i][j] = 0.0f;
    }

    for (int kt = 0; kt <= qt; ++kt) {
        int kBase = kt * 64;
        __syncthreads();
        #pragma unroll
        for (int j = 0; j < 8; ++j) {
            int f = tid + j * 128;
            int rr = f >> 4, d4 = f & 15;
            *(float4*)(Ks + rr * 68 + d4 * 4) =
                *(const float4*)(kg + base + (size_t)(kBase + rr) * EMB + d4 * 4);
            *(float4*)(Vs + rr * 68 + d4 * 4) =
                *(const float4*)(vg + base + (size_t)(kBase + rr) * EMB + d4 * 4);
        }
        __syncthreads();

        // scores: s[4 rows][8 cols]
        float s[4][8];
        #pragma unroll
        for (int i = 0; i < 4; ++i)
            #pragma unroll
            for (int j = 0; j < 8; ++j) s[i][j] = 0.0f;

        #pragma unroll
        for (int d4 = 0; d4 < 16; ++d4) {
            float4 qv[4];
            #pragma unroll
            for (int i = 0; i < 4; ++i)
                qv[i] = *(const float4*)(Qs + (ty + 16 * i) * 68 + d4 * 4);
            #pragma unroll
            for (int j = 0; j < 8; ++j) {
                float4 kv = *(const float4*)(Ks + (tx * 8 + j) * 68 + d4 * 4);
                #pragma unroll
                for (int i = 0; i < 4; ++i) {
                    s[i][j] = fmaf(qv[i].x, kv.x, s[i][j]);
                    s[i][j] = fmaf(qv[i].y, kv.y, s[i][j]);
                    s[i][j] = fmaf(qv[i].z, kv.z, s[i][j]);
                    s[i][j] = fmaf(qv[i].w, kv.w, s[i][j]);
                }
            }
        }

        bool diag = (kt == qt);
        #pragma unroll
        for (int i = 0; i < 4; ++i) {
            int R = ty + 16 * i;
            float mx = -1e30f;
            #pragma unroll
            for (int j = 0; j < 8; ++j) {
                float sv = s[i][j] * 0.125f;
                if (diag && (tx * 8 + j > R)) sv = -1e30f;
                s[i][j] = sv;
                mx = fmaxf(mx, sv);
            }
            mx = fmaxf(mx, __shfl_xor_sync(0xffffffffu, mx, 1));
            mx = fmaxf(mx, __shfl_xor_sync(0xffffffffu, mx, 2));
            mx = fmaxf(mx, __shfl_xor_sync(0xffffffffu, mx, 4));
            float mnew = fmaxf(m[i], mx);
            float corr = __expf(m[i] - mnew);
            float p[8], psum = 0.0f;
            #pragma unroll
            for (int j = 0; j < 8; ++j) { p[j] = __expf(s[i][j] - mnew); psum += p[j]; }
            *(float4*)(Ps + R * 68 + tx * 8)     = make_float4(p[0], p[1], p[2], p[3]);
            *(float4*)(Ps + R * 68 + tx * 8 + 4) = make_float4(p[4], p[5], p[6], p[7]);
            psum += __shfl_xor_sync(0xffffffffu, psum, 1);
            psum += __shfl_xor_sync(0xffffffffu, psum, 2);
            psum += __shfl_xor_sync(0xffffffffu, psum, 4);
            l[i] = l[i] * corr + psum;
            m[i] = mnew;
            #pragma unroll
            for (int j = 0; j < 8; ++j) acc[i][j] *= corr;
        }
        __syncwarp();

        // PV: acc[4 rows][8 d-cols] += P[row][s] * V[s][d]
        #pragma unroll
        for (int s4 = 0; s4 < 16; ++s4) {
            float4 pv[4];
            #pragma unroll
            for (int i = 0; i < 4; ++i)
                pv[i] = *(const float4*)(Ps + (ty + 16 * i) * 68 + s4 * 4);
            #pragma unroll
            for (int ss = 0; ss < 4; ++ss) {
                const float* vr = Vs + (s4 * 4 + ss) * 68 + tx * 8;
                float4 v0 = *(const float4*)(vr);
                float4 v1 = *(const float4*)(vr + 4);
                #pragma unroll
                for (int i = 0; i < 4; ++i) {
                    float p = (ss == 0) ? pv[i].x : (ss == 1) ? pv[i].y :
                              (ss == 2) ? pv[i].z : pv[i].w;
                    acc[i][0] = fmaf(p, v0.x, acc[i][0]);
                    acc[i][1] = fmaf(p, v0.y, acc[i][1]);
                    acc[i][2] = fmaf(p, v0.z, acc[i][2]);
                    acc[i][3] = fmaf(p, v0.w, acc[i][3]);
                    acc[i][4] = fmaf(p, v1.x, acc[i][4]);
                    acc[i][5] = fmaf(p, v1.y, acc[i][5]);
                    acc[i][6] = fmaf(p, v1.z, acc[i][6]);
                    acc[i][7] = fmaf(p, v1.w, acc[i][7]);
                }
            }
        }
        __syncwarp();
    }

    #pragma unroll
    for (int i = 0; i < 4; ++i) {
        float inv = 1.0f / l[i];
        size_t off = base + (size_t)(qBase + ty + 16 * i) * EMB + tx * 8;
        #pragma unroll
        for (int j = 0; j < 8; j += 2) {
            float v0 = acc[i][j] * inv, v1 = acc[i][j + 1] * inv;
            float h0 = __bfloat162float(__float2bfloat16(v0));
            float h1 = __bfloat162float(__float2bfloat16(v1));
            *(uint32_t*)(oh + off + j) = pack_bf2(v0, v1);
            *(uint32_t*)(ol + off + j) = pack_bf2(v0 - h0, v1 - h1);
        }
    }
}

// ---------------- launch ----------------------------------------------------
extern "C" void kernel_launch(void* const* d_in, const int* in_sizes, int n_in,
                              void* d_out, int out_size) {
    const int*   idx    = (const int*)d_in[0];
    const float* tok    = (const float*)d_in[1];
    const float* pos    = (const float*)d_in[2];
    const float* Wq     = (const float*)d_in[3];
    const float* Wk     = (const float*)d_in[4];
    const float* Wv     = (const float*)d_in[5];
    const float* Wp     = (const float*)d_in[6];
    const float* bp     = (const float*)d_in[7];
    const float* ln1_g  = (const float*)d_in[8];
    const float* ln1_b  = (const float*)d_in[9];
    const float* ln2_g  = (const float*)d_in[10];
    const float* ln2_b  = (const float*)d_in[11];
    const float* W1     = (const float*)d_in[12];
    const float* b1     = (const float*)d_in[13];
    const float* W2     = (const float*)d_in[14];
    const float* b2     = (const float*)d_in[15];
    const float* lnf_g  = (const float*)d_in[16];
    const float* lnf_b  = (const float*)d_in[17];
    const float* Wout   = (const float*)d_in[18];

    float *x, *q, *k, *v;
    bf16 *hh, *hl, *ohh, *ohl, *uh, *ul;
    bf16 *wqh, *wql, *wkh, *wkl, *wvh, *wvl, *wph, *wpl, *w1h, *w1l, *w2h, *w2l, *woh, *wol;
    cudaGetSymbolAddress((void**)&x, g_x);
    cudaGetSymbolAddress((void**)&q, g_q);
    cudaGetSymbolAddress((void**)&k, g_k);
    cudaGetSymbolAddress((void**)&v, g_v);
    cudaGetSymbolAddress((void**)&hh, g_h_h);
    cudaGetSymbolAddress((void**)&hl, g_h_l);
    cudaGetSymbolAddress((void**)&ohh, g_o_h);
    cudaGetSymbolAddress((void**)&ohl, g_o_l);
    cudaGetSymbolAddress((void**)&uh, g_u_h);
    cudaGetSymbolAddress((void**)&ul, g_u_l);
    cudaGetSymbolAddress((void**)&wqh, g_Wq_h); cudaGetSymbolAddress((void**)&wql, g_Wq_l);
    cudaGetSymbolAddress((void**)&wkh, g_Wk_h); cudaGetSymbolAddress((void**)&wkl, g_Wk_l);
    cudaGetSymbolAddress((void**)&wvh, g_Wv_h); cudaGetSymbolAddress((void**)&wvl, g_Wv_l);
    cudaGetSymbolAddress((void**)&wph, g_Wp_h); cudaGetSymbolAddress((void**)&wpl, g_Wp_l);
    cudaGetSymbolAddress((void**)&w1h, g_W1_h); cudaGetSymbolAddress((void**)&w1l, g_W1_l);
    cudaGetSymbolAddress((void**)&w2h, g_W2_h); cudaGetSymbolAddress((void**)&w2l, g_W2_l);
    cudaGetSymbolAddress((void**)&woh, g_Wo_h); cudaGetSymbolAddress((void**)&wol, g_Wo_l);

    cudaFuncSetAttribute(mgemm2_kernel, cudaFuncAttributeMaxDynamicSharedMemorySize, MG_SMEM);
    cudaFuncSetAttribute(fattn_kernel, cudaFuncAttributeMaxDynamicSharedMemorySize, FA_SMEM);

    dim3 tcb(32, 8);
    tconv_kernel<<<dim3(EMB/32, EMB/32, NL), tcb>>>(Wq, wqh, wql, EMB, EMB);
    tconv_kernel<<<dim3(EMB/32, EMB/32, NL), tcb>>>(Wk, wkh, wkl, EMB, EMB);
    tconv_kernel<<<dim3(EMB/32, EMB/32, NL), tcb>>>(Wv, wvh, wvl, EMB, EMB);
    tconv_kernel<<<dim3(EMB/32, EMB/32, NL), tcb>>>(Wp, wph, wpl, EMB, EMB);
    tconv_kernel<<<dim3(HID/32, EMB/32, NL), tcb>>>(W1, w1h, w1l, EMB, HID);
    tconv_kernel<<<dim3(EMB/32, HID/32, NL), tcb>>>(W2, w2h, w2l, HID, EMB);
    tconv_kernel<<<dim3(VOCAB/32, EMB/32, 1), tcb>>>(Wout, woh, wol, EMB, VOCAB);

    embed_kernel<<<NTOK, 256>>>(idx, tok, pos, x);

    dim3 gE(NTOK / 128, EMB / 128);     // 32 x 8
    dim3 gH(NTOK / 128, HID / 128);     // 32 x 32
    dim3 gV(NTOK / 128, VOCAB / 128);   // 32 x 250
    dim3 gA(SEQ / 64, 2 * NH);          // 32 x 32

    for (int l = 0; l < NL; l++) {
        size_t wo = (size_t)l * EMB * EMB;
        size_t w1o = (size_t)l * EMB * HID;

        ln_kernel<<<NTOK, 256>>>(x, ln1_g + l * EMB, ln1_b + l * EMB, hh, hl);
        mgemm2_kernel<<<gE, 256, MG_SMEM>>>(hh, hl, wqh + wo, wql + wo, nullptr, nullptr,
                                            q, nullptr, nullptr, NTOK, EMB, EMB, 0);
        mgemm2_kernel<<<gE, 256, MG_SMEM>>>(hh, hl, wkh + wo, wkl + wo, nullptr, nullptr,
                                            k, nullptr, nullptr, NTOK, EMB, EMB, 0);
        mgemm2_kernel<<<gE, 256, MG_SMEM>>>(hh, hl, wvh + wo, wvl + wo, nullptr, nullptr,
                                            v, nullptr, nullptr, NTOK, EMB, EMB, 0);
        fattn_kernel<<<gA, 128, FA_SMEM>>>(q, k, v, ohh, ohl);
        mgemm2_kernel<<<gE, 256, MG_SMEM>>>(ohh, ohl, wph + wo, wpl + wo, bp + l * EMB, x,
                                            x, nullptr, nullptr, NTOK, EMB, EMB,
                                            FLAG_BIAS | FLAG_RES);
        ln_kernel<<<NTOK, 256>>>(x, ln2_g + l * EMB, ln2_b + l * EMB, hh, hl);
        mgemm2_kernel<<<gH, 256, MG_SMEM>>>(hh, hl, w1h + w1o, w1l + w1o, b1 + l * HID,
                                            nullptr, nullptr, uh, ul, NTOK, HID, EMB,
                                            FLAG_BIAS | FLAG_GELU | FLAG_OSPL);
        mgemm2_kernel<<<gE, 256, MG_SMEM>>>(uh, ul, w2h + w1o, w2l + w1o, b2 + l * EMB, x,
                                            x, nullptr, nullptr, NTOK, EMB, HID,
                                            FLAG_BIAS | FLAG_RES);
    }

    ln_kernel<<<NTOK, 256>>>(x, lnf_g, lnf_b, hh, hl);
    mgemm2_kernel<<<gV, 256, MG_SMEM>>>(hh, hl, woh, wol, nullptr, nullptr,
                                        (float*)d_out, nullptr, nullptr,
                                        NTOK, VOCAB, EMB, 0);
}